// round 17
// baseline (speedup 1.0000x reference)
#include <cuda_runtime.h>

typedef unsigned long long ULL;

// ---------------- scratch (static device globals; no allocation) ----------------
static __device__ float g_gi[500 * 1024 * 300];     // 614.4 MB: encoder gi
static __device__ float g_gid[80 * 1024 * 300];     // 98.3 MB: decoder gi (both layers)
static __device__ float g_buf0[500 * 1024 * 100];   // 204.8 MB: encoder e0 sequence
static __device__ float g_bufd[80 * 1024 * 100];    // decoder d0 sequence
static __device__ float g_d1[80 * 1024 * 100];      // decoder layer-1 outputs
static __device__ float g_decin[80 * 1024 * 26];    // embedded decoder inputs
static __device__ float g_h0[1024 * 100];           // h_enc0 (also reused as gru-d1 chunk carry)
static __device__ float g_h1[1024 * 100];           // h_enc1

// ---------------- f32x2 helpers ----------------
__device__ __forceinline__ ULL pack2(float lo, float hi) {
    ULL r;
    asm("mov.b64 %0, {%1, %2};" : "=l"(r) : "f"(lo), "f"(hi));
    return r;
}
__device__ __forceinline__ void unpack2(ULL v, float& lo, float& hi) {
    asm("mov.b64 {%0, %1}, %2;" : "=f"(lo), "=f"(hi) : "l"(v));
}
__device__ __forceinline__ void fma2(ULL& d, ULL a, ULL b) {
    asm("fma.rn.f32x2 %0, %1, %2, %0;" : "+l"(d) : "l"(a), "l"(b));
}

// ---------------- accurate activations (immune to fast-math flags) ----------------
__device__ __forceinline__ float exp_acc(float x) {
    float z = x * 1.4426950408889634f;
    float n = rintf(z);
    float r = fmaf(n, -0.693147182464599609375f, x);
    r = fmaf(n, 1.9046542121259336e-9f, r);
    float p = 1.9841270114e-4f;
    p = fmaf(p, r, 1.3888888877e-3f);
    p = fmaf(p, r, 8.3333337680e-3f);
    p = fmaf(p, r, 4.1666667908e-2f);
    p = fmaf(p, r, 1.6666667163e-1f);
    p = fmaf(p, r, 0.5f);
    p = fmaf(p, r, 1.0f);
    p = fmaf(p, r, 1.0f);
    int i = (int)n;
    float sc = __int_as_float((i + 127) << 23);
    return p * sc;
}
__device__ __forceinline__ float sigm(float x) {
    float xc = fminf(fmaxf(x, -30.0f), 30.0f);
    float s = exp_acc(-xc);
    return __fdiv_rn(1.0f, 1.0f + s);
}
__device__ __forceinline__ float tanh_acc(float x) {
    float ax = fabsf(x);
    float t;
    if (ax < 0.25f) {
        float x2 = x * x;
        float p = 0.021869488536155203f;
        p = fmaf(p, x2, -0.05396825396825397f);
        p = fmaf(p, x2, 0.13333333333333333f);
        p = fmaf(p, x2, -0.3333333333333333f);
        p = fmaf(p, x2, 1.0f);
        t = x * p;
    } else {
        float a = fminf(ax, 9.0f);
        float s = exp_acc(-2.0f * a);
        t = __fdiv_rn(1.0f - s, 1.0f + s);
        t = copysignf(t, x);
    }
    return t;
}

// ---------------- embedding gather ----------------
__global__ void k_embed(const int* __restrict__ tgt,
                        const float* __restrict__ emb,
                        float* __restrict__ out) {
    int idx = blockIdx.x * blockDim.x + threadIdx.x;
    const int total = 80 * 1024 * 26;
    if (idx < total) {
        int e  = idx % 26;
        int pb = idx / 26;
        int t = tgt[pb] & 63;
        out[idx] = emb[t * 26 + e];
    }
}

// ---------------- gi GEMM (2D register tile + distance-1 smem prefetch) ----------------
template <int K>
__global__ void __launch_bounds__(256) k_gemm(float* __restrict__ gi,
                                              const float* __restrict__ x,
                                              const float* __restrict__ W,
                                              const float* __restrict__ bih,
                                              const float* __restrict__ bhh) {
    const int MP = 132;
    const int BP = 68;
    extern __shared__ float sm[];
    float* As = sm;                  // [K+1][132]
    float* Bs = sm + (K + 1) * MP;   // [K+1][68]

    const int tid = threadIdx.x;
    const long n0 = (long)blockIdx.x * 128;
    const int  j0 = blockIdx.y * 64;

    for (int idx = tid; idx < 128 * K; idx += 256) {
        int m = idx / K, k = idx - m * K;
        As[k * MP + m] = x[(n0 + m) * K + k];
    }
    for (int idx = tid; idx < 64 * K; idx += 256) {
        int jj = idx / K, k = idx - jj * K;
        int j = j0 + jj;
        Bs[k * BP + jj] = (j < 300) ? W[j * K + k] : 0.0f;
    }
    __syncthreads();

    const int cx = tid & 15;
    const int ry = tid >> 4;

    ULL acc[4][4];
#pragma unroll
    for (int c = 0; c < 4; c++) {
        int j = j0 + cx * 4 + c;
        float bj = 0.0f;
        if (j < 300) bj = bih[j] + ((j < 200) ? bhh[j] : 0.0f);
        ULL b2 = pack2(bj, bj);
#pragma unroll
        for (int rp = 0; rp < 4; rp++) acc[c][rp] = b2;
    }

    const float* abase = As + ry * 8;
    const float* bbase = Bs + cx * 4;

    ulonglong2 a01 = *(const ulonglong2*)(abase);
    ulonglong2 a23 = *(const ulonglong2*)(abase + 4);
    float4     b4  = *(const float4*)(bbase);
#pragma unroll 4
    for (int k = 0; k < K; k++) {
        ulonglong2 a01c = a01, a23c = a23;
        float4     b4c  = b4;
        a01 = *(const ulonglong2*)(abase + (k + 1) * MP);
        a23 = *(const ulonglong2*)(abase + (k + 1) * MP + 4);
        b4  = *(const float4*)(bbase + (k + 1) * BP);
#pragma unroll
        for (int c = 0; c < 4; c++) {
            float bc = (c == 0) ? b4c.x : (c == 1) ? b4c.y : (c == 2) ? b4c.z : b4c.w;
            ULL w2 = pack2(bc, bc);
            fma2(acc[c][0], a01c.x, w2);
            fma2(acc[c][1], a01c.y, w2);
            fma2(acc[c][2], a23c.x, w2);
            fma2(acc[c][3], a23c.y, w2);
        }
    }

    if (j0 + cx * 4 < 300) {
        float v[4][8];
#pragma unroll
        for (int c = 0; c < 4; c++)
#pragma unroll
            for (int rp = 0; rp < 4; rp++)
                unpack2(acc[c][rp], v[c][2 * rp], v[c][2 * rp + 1]);
#pragma unroll
        for (int r = 0; r < 8; r++) {
            float4 f;
            f.x = v[0][r]; f.y = v[1][r]; f.z = v[2][r]; f.w = v[3][r];
            *(float4*)(gi + (n0 + ry * 8 + r) * 300 + j0 + cx * 4) = f;
        }
    }
}

// ---------------- persistent GRU recurrence (2 blocks/SM, <=4 rows/block) ----------------
// 296 blocks: b<136 -> rows 4b..4b+3 (nr=4); b>=136 -> rows 544+3(b-136).. (nr=3).
// 320 threads, 300 active: thread = column j. W: k<40 in regs, k>=40 in smem (stride 61)
// with explicit distance-2 double-buffer prefetch (load scheduling only -> bitwise safe).
__global__ void __launch_bounds__(320, 2) k_gru(const float* __restrict__ gi,
                                                const float* __restrict__ Whh,
                                                const float* __restrict__ bhh,
                                                const float* __restrict__ h0,
                                                float* __restrict__ y,
                                                float* __restrict__ hfin,
                                                int T) {
    extern __shared__ float sm[];
    float* hs  = sm;            // [104][4]: hs[k*4+r], k>=100 zero pad (prefetch overrun)
    float* rsT = sm + 416;      // [4][100] raw r-gate sums
    float* zsT = rsT + 400;     // [4][100] raw z-gate sums
    float* asT = zsT + 400;     // [4][100] n-gate input part
    float* bsT = asT + 400;     // [4][100] n-gate hidden part
    float* Ws2 = bsT + 400;     // [300][61]: W[j][40+k2], stride 61 (odd -> conflict-free)

    const int tid = threadIdx.x;
    const int bx  = blockIdx.x;
    const int b0  = (bx < 136) ? bx * 4 : 544 + (bx - 136) * 3;
    const int nr  = (bx < 136) ? 4 : 3;
    const bool active = tid < 300;
    const int j = active ? tid : 0;
    const int g = (j >= 200) ? 2 : (j >= 100) ? 1 : 0;
    const int u = j - g * 100;

    for (int idx = tid; idx < 416; idx += 320) {
        int r = idx & 3, k = idx >> 2;
        hs[idx] = (k < 100 && r < nr && h0) ? h0[(b0 + r) * 100 + k] : 0.0f;
    }
    for (int idx = tid; idx < 300 * 60; idx += 320) {
        int jj = idx / 60, k2 = idx - jj * 60;
        Ws2[jj * 61 + k2] = Whh[jj * 100 + 40 + k2];
    }

    // W[j][0..39] -> registers (Whh + j*100 floats = 400j bytes: 16B aligned)
    float wreg[40];
    {
        const float4* wp = (const float4*)(Whh + j * 100);
#pragma unroll
        for (int k4 = 0; k4 < 10; k4++) {
            float4 w = wp[k4];
            wreg[k4 * 4 + 0] = w.x;
            wreg[k4 * 4 + 1] = w.y;
            wreg[k4 * 4 + 2] = w.z;
            wreg[k4 * 4 + 3] = w.w;
        }
    }
    const float bnn = (active && g == 2) ? bhh[j] : 0.0f;
    const float* wsrow = Ws2 + j * 61 - 40;

    // cross-step gi prefetch
    float gvc[4];
#pragma unroll
    for (int r = 0; r < 4; r++) gvc[r] = 0.0f;
    if (active) {
        const float* gp = gi + ((long)0 * 1024 + b0) * 300 + j;
        for (int r = 0; r < nr; r++) gvc[r] = gp[r * 300];
    }
    __syncthreads();

    for (int t = 0; t < T; t++) {
        float gvn[4];
#pragma unroll
        for (int r = 0; r < 4; r++) gvn[r] = 0.0f;
        if (active) {
            if (t + 1 < T) {
                const float* gp = gi + ((long)(t + 1) * 1024 + b0) * 300 + j;
                for (int r = 0; r < nr; r++) gvn[r] = gp[r * 300];
            }

            // w double-buffer prologue: pairs for kk=20 (k=40,41) and kk=21 (k=42,43)
            float bufA0 = wsrow[40], bufA1 = wsrow[41];
            float bufB0 = wsrow[42], bufB1 = wsrow[43];

            // matvec: rows 0-3, lanes = row pairs; k-ascending chains;
            // h distance-2 prefetch + w distance-2 double buffer
            ULL a01 = 0, a23 = 0;
            ulonglong2 h0v = *(const ulonglong2*)(hs + 0);
            ulonglong2 h1v = *(const ulonglong2*)(hs + 4);
#pragma unroll
            for (int kk = 0; kk < 50; kk++) {
                const int k0 = 2 * kk, k1 = 2 * kk + 1;
                ulonglong2 c0 = h0v, c1 = h1v;
                // prefetch k0+2, k1+2 (kk=49 -> k=100,101 zero pad, unused)
                h0v = *(const ulonglong2*)(hs + (k0 + 2) * 4);
                h1v = *(const ulonglong2*)(hs + (k1 + 2) * 4);
                float w0, w1;
                if (k1 < 40) {
                    w0 = wreg[k0];
                    w1 = wreg[k1];
                } else {
                    if (kk & 1) { w0 = bufB0; w1 = bufB1; }
                    else        { w0 = bufA0; w1 = bufA1; }
                    if (kk + 2 < 50) {
                        if (kk & 1) { bufB0 = wsrow[k0 + 4]; bufB1 = wsrow[k1 + 4]; }
                        else        { bufA0 = wsrow[k0 + 4]; bufA1 = wsrow[k1 + 4]; }
                    }
                }
                ULL w2 = pack2(w0, w0);
                fma2(a01, c0.x, w2);
                fma2(a23, c0.y, w2);
                w2 = pack2(w1, w1);
                fma2(a01, c1.x, w2);
                fma2(a23, c1.y, w2);
            }
            float ah[4];
            unpack2(a01, ah[0], ah[1]);
            unpack2(a23, ah[2], ah[3]);

            // store RAW gate sums (activations deferred to phase B)
            if (g == 0) {
#pragma unroll
                for (int r = 0; r < 4; r++) rsT[r * 100 + u] = gvc[r] + ah[r];
            } else if (g == 1) {
#pragma unroll
                for (int r = 0; r < 4; r++) zsT[r * 100 + u] = gvc[r] + ah[r];
            } else {
#pragma unroll
                for (int r = 0; r < 4; r++) {
                    asT[r * 100 + u] = gvc[r];
                    bsT[r * 100 + u] = ah[r] + bnn;
                }
            }
        }
        __syncthreads();
        // Phase B: all activations + h update, distributed over 300 threads (<=2 cells)
        if (active) {
            for (int c = tid; c < nr * 100; c += 300) {
                int r = c / 100, uu = c - r * 100;
                float rr = sigm(rsT[c]);
                float zz = sigm(zsT[c]);
                float av = asT[c];
                float bv = bsT[c];
                float ho = hs[uu * 4 + r];
                float nn = tanh_acc(fmaf(rr, bv, av));
                float hn = fmaf(zz, ho - nn, nn);
                hs[uu * 4 + r] = hn;
                if (y) y[((long)t * 1024 + b0 + r) * 100 + uu] = hn;
                if (hfin && t == T - 1) hfin[(b0 + r) * 100 + uu] = hn;
            }
        }
        __syncthreads();
#pragma unroll
        for (int r = 0; r < 4; r++) gvc[r] = gvn[r];
    }
}

// ---------------- logits + argmax + target_cal (chunkable via block_off) ----------------
__global__ void __launch_bounds__(1024) k_out(float* __restrict__ out,
                                              const float* __restrict__ d1,
                                              const float* __restrict__ W,
                                              const float* __restrict__ b,
                                              const int* __restrict__ tgt,
                                              int block_off) {
    __shared__ float Ws[64 * 101];
    __shared__ float ds[16 * 100];
    __shared__ float ls[16 * 64];
    const int tid = threadIdx.x;
    const int bx  = blockIdx.x + block_off;

    for (int idx = tid; idx < 64 * 101; idx += 1024) {
        int d = idx / 101, k = idx - d * 101;
        Ws[idx] = (k < 100) ? W[d * 100 + k] : 0.0f;
    }
    const long r0 = (long)bx * 16;
    for (int idx = tid; idx < 1600; idx += 1024) {
        int rr = idx / 100, k = idx - rr * 100;
        ds[idx] = d1[(r0 + rr) * 100 + k];
    }
    __syncthreads();

    const int rr = tid >> 6;
    const int d  = tid & 63;
    const float* dp = ds + rr * 100;
    const float* wp = Ws + d * 101;
    float a0 = b[d], a1 = 0.0f;
#pragma unroll 2
    for (int k = 0; k < 100; k += 2) {
        a0 = fmaf(dp[k],     wp[k],     a0);
        a1 = fmaf(dp[k + 1], wp[k + 1], a1);
    }
    float acc = a0 + a1;

    const long row = r0 + rr;
    out[row * 64 + d] = acc;
    ls[rr * 64 + d] = acc;
    __syncthreads();

    if (d == 0) {
        float best = ls[rr * 64];
        int bi = 0;
        for (int k = 1; k < 64; k++) {
            float v = ls[rr * 64 + k];
            if (v > best) { best = v; bi = k; }
        }
        out[5177344 + row] = (float)tgt[row + 1024];
        out[5258240 + row] = (float)bi;
    }
}

// ---------------- launch ----------------
extern "C" void kernel_launch(void* const* d_in, const int* in_sizes, int n_in,
                              void* d_out, int out_size) {
    const float* x     = (const float*)d_in[0];
    const int*   tgt   = (const int*)d_in[1];
    const float* emb   = (const float*)d_in[2];
    const float* eWih0 = (const float*)d_in[3];
    const float* eWhh0 = (const float*)d_in[4];
    const float* ebih0 = (const float*)d_in[5];
    const float* ebhh0 = (const float*)d_in[6];
    const float* eWih1 = (const float*)d_in[7];
    const float* eWhh1 = (const float*)d_in[8];
    const float* ebih1 = (const float*)d_in[9];
    const float* ebhh1 = (const float*)d_in[10];
    const float* dWih0 = (const float*)d_in[11];
    const float* dWhh0 = (const float*)d_in[12];
    const float* dbih0 = (const float*)d_in[13];
    const float* dbhh0 = (const float*)d_in[14];
    const float* dWih1 = (const float*)d_in[15];
    const float* dWhh1 = (const float*)d_in[16];
    const float* dbih1 = (const float*)d_in[17];
    const float* dbhh1 = (const float*)d_in[18];
    const float* linW  = (const float*)d_in[19];
    const float* linb  = (const float*)d_in[20];
    float* out = (float*)d_out;

    float *gi, *gid, *buf0, *bufd, *d1b, *decin, *h0b, *h1b;
    cudaGetSymbolAddress((void**)&gi,    g_gi);
    cudaGetSymbolAddress((void**)&gid,   g_gid);
    cudaGetSymbolAddress((void**)&buf0,  g_buf0);
    cudaGetSymbolAddress((void**)&bufd,  g_bufd);
    cudaGetSymbolAddress((void**)&d1b,   g_d1);
    cudaGetSymbolAddress((void**)&decin, g_decin);
    cudaGetSymbolAddress((void**)&h0b,   g_h0);
    cudaGetSymbolAddress((void**)&h1b,   g_h1);

    static cudaStream_t s2 = nullptr, s5 = nullptr;
    static cudaEvent_t eF = nullptr, eH0 = nullptr, eH1 = nullptr, eE = nullptr,
                       eP1 = nullptr, eK1 = nullptr;
    if (!s2) {
        cudaStreamCreateWithFlags(&s2, cudaStreamNonBlocking);
        cudaStreamCreateWithFlags(&s5, cudaStreamNonBlocking);
        cudaEventCreateWithFlags(&eF,  cudaEventDisableTiming);
        cudaEventCreateWithFlags(&eH0, cudaEventDisableTiming);
        cudaEventCreateWithFlags(&eH1, cudaEventDisableTiming);
        cudaEventCreateWithFlags(&eE,  cudaEventDisableTiming);
        cudaEventCreateWithFlags(&eP1, cudaEventDisableTiming);
        cudaEventCreateWithFlags(&eK1, cudaEventDisableTiming);
    }

    const int SMEM_G26  = ((26 + 1) * 132 + (26 + 1) * 68) * 4;     // 21,600 B
    const int SMEM_G100 = ((100 + 1) * 132 + (100 + 1) * 68) * 4;   // 80,800 B
    const int SMEM_GRU  = (416 + 4 * 400 + 300 * 61) * 4;           // 81,264 B (x2/SM fits)
    cudaFuncSetAttribute((const void*)k_gemm<26>,
                         cudaFuncAttributeMaxDynamicSharedMemorySize, SMEM_G26);
    cudaFuncSetAttribute((const void*)k_gemm<100>,
                         cudaFuncAttributeMaxDynamicSharedMemorySize, SMEM_G100);
    cudaFuncSetAttribute((const void*)k_gru,
                         cudaFuncAttributeMaxDynamicSharedMemorySize, SMEM_GRU);

    // ---- fork: decoder-independent prep on s2 ----
    cudaEventRecord(eF, 0);
    cudaStreamWaitEvent(s2, eF, 0);
    k_embed<<<(80 * 1024 * 26 + 255) / 256, 256, 0, s2>>>(tgt, emb, decin);
    k_gemm<26><<<dim3(640, 5), 256, SMEM_G26, s2>>>(gid, decin, dWih0, dbih0, dbhh0);

    // ---- encoder on capture stream ----
    k_gemm<26><<<dim3(4000, 5), 256, SMEM_G26>>>(gi, x, eWih0, ebih0, ebhh0);
    k_gru<<<296, 320, SMEM_GRU>>>(gi, eWhh0, ebhh0, nullptr, buf0, h0b, 500);
    cudaEventRecord(eH0, 0);
    k_gemm<100><<<dim3(4000, 5), 256, SMEM_G100>>>(gi, buf0, eWih1, ebih1, ebhh1);
    k_gru<<<296, 320, SMEM_GRU>>>(gi, eWhh1, ebhh1, nullptr, nullptr, h1b, 500);
    cudaEventRecord(eH1, 0);

    // ---- decoder on s2 (overlaps encoder layer 1) ----
    cudaStreamWaitEvent(s2, eH0, 0);
    k_gru<<<296, 320, SMEM_GRU, s2>>>(gid, dWhh0, dbhh0, h0b, bufd, nullptr, 80);
    k_gemm<100><<<dim3(640, 5), 256, SMEM_G100, s2>>>(gid, bufd, dWih1, dbih1, dbhh1);
    cudaStreamWaitEvent(s2, eH1, 0);
    // gru-d1 split into two T=40 chunks; h carried exactly through h0b (free by now)
    k_gru<<<296, 320, SMEM_GRU, s2>>>(gid, dWhh1, dbhh1, h1b, d1b, h0b, 40);
    cudaEventRecord(eP1, s2);
    k_gru<<<296, 320, SMEM_GRU, s2>>>(gid + (long)40 * 1024 * 300, dWhh1, dbhh1,
                                      h0b, d1b + (long)40 * 1024 * 100, nullptr, 40);
    // k_out chunk 1 (rows for t<40) overlaps gru-d1 part 2
    cudaStreamWaitEvent(s5, eP1, 0);
    k_out<<<2560, 1024, 0, s5>>>(out, d1b, linW, linb, tgt, 0);
    cudaEventRecord(eK1, s5);
    // k_out chunk 2 (remaining rows) after gru-d1 part 2
    k_out<<<2496, 1024, 0, s2>>>(out, d1b, linW, linb, tgt, 2560);

    // ---- join ----
    cudaEventRecord(eE, s2);
    cudaStreamWaitEvent(0, eE, 0);
    cudaStreamWaitEvent(0, eK1, 0);
}